// round 6
// baseline (speedup 1.0000x reference)
#include <cuda_runtime.h>
#include <cuda_bf16.h>
#include <math.h>

// Fixed problem shapes
#define T_DIM 2048
#define B_DIM 2
#define E_DIM 1024
#define H_DIM 16
#define D_DIM 64
#define M_DIM (T_DIM * B_DIM)   // 4096 rows for projections

// Scratch (allocation-free rule: __device__ globals)
__device__ float g_Q[B_DIM * H_DIM * T_DIM * D_DIM];   // [B,H,T,d], pre-scaled
__device__ float g_K[B_DIM * H_DIM * T_DIM * D_DIM];
__device__ float g_V[B_DIM * H_DIM * T_DIM * D_DIM];
__device__ float g_ctx[M_DIM * E_DIM];                 // [T,B,E]

// ---------------------------------------------------------------------------
// Tiled GEMM: C[m,f] = sum_e A[m,e] * W[f,e] + bias[f]
// Block tile 128x128, K-tile 16, 256 threads, 8x8 per thread.
// ---------------------------------------------------------------------------
#define BM 128
#define BN 128
#define BK 16
#define TM 8
#define TN 8

// Epilogue 0: scatter QKV (N = 3*E). Epilogue 1: write to out (N = E).
__global__ __launch_bounds__(256, 2)
void gemm_qkv_kernel(const float* __restrict__ A,
                     const float* __restrict__ W,
                     const float* __restrict__ bias) {
    __shared__ float As[BK][BM];
    __shared__ float Ws[BK][BN];

    const int bm = blockIdx.y * BM;
    const int bn = blockIdx.x * BN;
    const int tid = threadIdx.x;
    const int ty = tid >> 4;       // 0..15 (M direction)
    const int tx = tid & 15;       // 0..15 (N direction)

    float acc[TM][TN];
#pragma unroll
    for (int i = 0; i < TM; i++)
#pragma unroll
        for (int j = 0; j < TN; j++) acc[i][j] = 0.0f;

    for (int k0 = 0; k0 < E_DIM; k0 += BK) {
        // Load A tile (128 rows x 16 k) and W tile, transposed into smem
#pragma unroll
        for (int i = tid; i < BM * BK / 4; i += 256) {
            int row = i >> 2;
            int kq  = (i & 3) << 2;
            float4 v = *(const float4*)(A + (size_t)(bm + row) * E_DIM + k0 + kq);
            As[kq + 0][row] = v.x; As[kq + 1][row] = v.y;
            As[kq + 2][row] = v.z; As[kq + 3][row] = v.w;
        }
#pragma unroll
        for (int i = tid; i < BN * BK / 4; i += 256) {
            int row = i >> 2;
            int kq  = (i & 3) << 2;
            float4 v = *(const float4*)(W + (size_t)(bn + row) * E_DIM + k0 + kq);
            Ws[kq + 0][row] = v.x; Ws[kq + 1][row] = v.y;
            Ws[kq + 2][row] = v.z; Ws[kq + 3][row] = v.w;
        }
        __syncthreads();

#pragma unroll
        for (int kk = 0; kk < BK; kk++) {
            float a[TM], b[TN];
#pragma unroll
            for (int i = 0; i < TM; i++) a[i] = As[kk][ty * TM + i];
#pragma unroll
            for (int j = 0; j < TN; j++) b[j] = Ws[kk][tx * TN + j];
#pragma unroll
            for (int i = 0; i < TM; i++)
#pragma unroll
                for (int j = 0; j < TN; j++)
                    acc[i][j] = fmaf(a[i], b[j], acc[i][j]);
        }
        __syncthreads();
    }

    // Epilogue: add bias, scale q, scatter to g_Q/g_K/g_V in [B,H,T,d]
#pragma unroll
    for (int i = 0; i < TM; i++) {
        int m = bm + ty * TM + i;
        int t = m >> 1;          // B_DIM == 2
        int b = m & 1;
#pragma unroll
        for (int j = 0; j < TN; j++) {
            int f = bn + tx * TN + j;
            float v = acc[i][j] + bias[f];
            int h  = f / (3 * D_DIM);
            int r  = f - h * (3 * D_DIM);
            int jj = r >> 6;             // D_DIM == 64
            int dd = r & 63;
            size_t idx = (((size_t)(b * H_DIM + h)) * T_DIM + t) * D_DIM + dd;
            if (jj == 0)      g_Q[idx] = v * 0.125f;   // 1/sqrt(64)
            else if (jj == 1) g_K[idx] = v;
            else              g_V[idx] = v;
        }
    }
}

__global__ __launch_bounds__(256, 2)
void gemm_out_kernel(const float* __restrict__ W,
                     const float* __restrict__ bias,
                     float* __restrict__ out) {
    __shared__ float As[BK][BM];
    __shared__ float Ws[BK][BN];

    const int bm = blockIdx.y * BM;
    const int bn = blockIdx.x * BN;
    const int tid = threadIdx.x;
    const int ty = tid >> 4;
    const int tx = tid & 15;

    float acc[TM][TN];
#pragma unroll
    for (int i = 0; i < TM; i++)
#pragma unroll
        for (int j = 0; j < TN; j++) acc[i][j] = 0.0f;

    for (int k0 = 0; k0 < E_DIM; k0 += BK) {
#pragma unroll
        for (int i = tid; i < BM * BK / 4; i += 256) {
            int row = i >> 2;
            int kq  = (i & 3) << 2;
            float4 v = *(const float4*)(g_ctx + (size_t)(bm + row) * E_DIM + k0 + kq);
            As[kq + 0][row] = v.x; As[kq + 1][row] = v.y;
            As[kq + 2][row] = v.z; As[kq + 3][row] = v.w;
        }
#pragma unroll
        for (int i = tid; i < BN * BK / 4; i += 256) {
            int row = i >> 2;
            int kq  = (i & 3) << 2;
            float4 v = *(const float4*)(W + (size_t)(bn + row) * E_DIM + k0 + kq);
            Ws[kq + 0][row] = v.x; Ws[kq + 1][row] = v.y;
            Ws[kq + 2][row] = v.z; Ws[kq + 3][row] = v.w;
        }
        __syncthreads();

#pragma unroll
        for (int kk = 0; kk < BK; kk++) {
            float a[TM], b[TN];
#pragma unroll
            for (int i = 0; i < TM; i++) a[i] = As[kk][ty * TM + i];
#pragma unroll
            for (int j = 0; j < TN; j++) b[j] = Ws[kk][tx * TN + j];
#pragma unroll
            for (int i = 0; i < TM; i++)
#pragma unroll
                for (int j = 0; j < TN; j++)
                    acc[i][j] = fmaf(a[i], b[j], acc[i][j]);
        }
        __syncthreads();
    }

#pragma unroll
    for (int i = 0; i < TM; i++) {
        int m = bm + ty * TM + i;
#pragma unroll
        for (int j = 0; j < TN; j++) {
            int f = bn + tx * TN + j;
            out[(size_t)m * E_DIM + f] = acc[i][j] + bias[f];
        }
    }
}

// ---------------------------------------------------------------------------
// Flash-attention: one thread per query row. Q and accumulator in registers,
// K/V streamed through smem in 32-row tiles, online softmax in fp32.
// Grid: (T/128, B*H), 128 threads.
// ---------------------------------------------------------------------------
#define AT_BM 128
#define AT_BN 32

__global__ __launch_bounds__(128, 2)
void attn_kernel() {
    __shared__ float Ks[AT_BN][D_DIM];
    __shared__ float Vs[AT_BN][D_DIM];

    const int bh = blockIdx.y;                 // 0..31: b*H + h
    const int q0 = blockIdx.x * AT_BM;
    const int tid = threadIdx.x;

    const float* __restrict__ Qg = g_Q + (size_t)bh * T_DIM * D_DIM;
    const float* __restrict__ Kg = g_K + (size_t)bh * T_DIM * D_DIM;
    const float* __restrict__ Vg = g_V + (size_t)bh * T_DIM * D_DIM;

    float q[D_DIM], acc[D_DIM];
    {
        const float4* qr = (const float4*)(Qg + (size_t)(q0 + tid) * D_DIM);
#pragma unroll
        for (int i = 0; i < D_DIM / 4; i++) {
            float4 v = qr[i];
            q[4 * i + 0] = v.x; q[4 * i + 1] = v.y;
            q[4 * i + 2] = v.z; q[4 * i + 3] = v.w;
        }
    }
#pragma unroll
    for (int i = 0; i < D_DIM; i++) acc[i] = 0.0f;

    float mrun = -INFINITY;
    float lrun = 0.0f;

    for (int s0 = 0; s0 < T_DIM; s0 += AT_BN) {
        __syncthreads();
        // cooperative load of K/V tiles (32x64 each), fully coalesced
#pragma unroll
        for (int i = tid; i < AT_BN * D_DIM / 4; i += 128) {
            ((float4*)Ks)[i] = ((const float4*)(Kg + (size_t)s0 * D_DIM))[i];
            ((float4*)Vs)[i] = ((const float4*)(Vg + (size_t)s0 * D_DIM))[i];
        }
        __syncthreads();

        // scores for this thread's row vs 32 keys
        float s[AT_BN];
#pragma unroll
        for (int j = 0; j < AT_BN; j++) s[j] = 0.0f;
#pragma unroll
        for (int k = 0; k < D_DIM; k += 4) {
            float q0v = q[k], q1v = q[k + 1], q2v = q[k + 2], q3v = q[k + 3];
#pragma unroll
            for (int j = 0; j < AT_BN; j++) {
                float4 kv = *(const float4*)&Ks[j][k];
                s[j] = fmaf(q0v, kv.x,
                       fmaf(q1v, kv.y,
                       fmaf(q2v, kv.z,
                       fmaf(q3v, kv.w, s[j]))));
            }
        }

        // online softmax
        float mt = s[0];
#pragma unroll
        for (int j = 1; j < AT_BN; j++) mt = fmaxf(mt, s[j]);
        float mnew = fmaxf(mrun, mt);
        float scale = __expf(mrun - mnew);     // 0 on the first tile
        float p[AT_BN];
        float lsum = 0.0f;
#pragma unroll
        for (int j = 0; j < AT_BN; j++) {
            p[j] = __expf(s[j] - mnew);
            lsum += p[j];
        }
        lrun = lrun * scale + lsum;
#pragma unroll
        for (int i = 0; i < D_DIM; i++) acc[i] *= scale;

        // acc += P @ V
#pragma unroll
        for (int j = 0; j < AT_BN; j++) {
            float pj = p[j];
#pragma unroll
            for (int i = 0; i < D_DIM; i += 4) {
                float4 vv = *(const float4*)&Vs[j][i];
                acc[i + 0] = fmaf(pj, vv.x, acc[i + 0]);
                acc[i + 1] = fmaf(pj, vv.y, acc[i + 1]);
                acc[i + 2] = fmaf(pj, vv.z, acc[i + 2]);
                acc[i + 3] = fmaf(pj, vv.w, acc[i + 3]);
            }
        }
        mrun = mnew;
    }

    // normalize and write ctx as [T,B,E] with E index = h*64 + dd
    const int b = bh >> 4;           // H_DIM == 16
    const int h = bh & 15;
    const int t = q0 + tid;
    float inv_l = 1.0f / lrun;
    float* dst = g_ctx + ((size_t)t * B_DIM + b) * E_DIM + h * D_DIM;
#pragma unroll
    for (int i = 0; i < D_DIM; i += 4) {
        float4 v;
        v.x = acc[i + 0] * inv_l;
        v.y = acc[i + 1] * inv_l;
        v.z = acc[i + 2] * inv_l;
        v.w = acc[i + 3] * inv_l;
        *(float4*)(dst + i) = v;
    }
}

// ---------------------------------------------------------------------------
extern "C" void kernel_launch(void* const* d_in, const int* in_sizes, int n_in,
                              void* d_out, int out_size) {
    const float* query = (const float*)d_in[0];   // (T,B,E)
    const float* w_in  = (const float*)d_in[1];   // (3E,E)
    const float* b_in  = (const float*)d_in[2];   // (3E,)
    const float* w_out = (const float*)d_in[3];   // (E,E)
    const float* b_out = (const float*)d_in[4];   // (E,)
    float* out = (float*)d_out;                   // (T,B,E)

    dim3 g1(3 * E_DIM / BN, M_DIM / BM);          // 24 x 32
    gemm_qkv_kernel<<<g1, 256>>>(query, w_in, b_in);

    dim3 g2(T_DIM / AT_BM, B_DIM * H_DIM);        // 16 x 32
    attn_kernel<<<g2, 128>>>();

    dim3 g3(E_DIM / BN, M_DIM / BM);              // 8 x 32
    gemm_out_kernel<<<g3, 256>>>(w_out, b_out, out);
}

// round 9
// speedup vs baseline: 1.0531x; 1.0531x over previous
#include <cuda_runtime.h>
#include <cuda_bf16.h>
#include <math.h>

// Fixed problem shapes
#define T_DIM 2048
#define B_DIM 2
#define E_DIM 1024
#define H_DIM 16
#define D_DIM 64
#define M_DIM (T_DIM * B_DIM)   // 4096 rows for projections

typedef unsigned long long ull;

// ---- packed f32x2 helpers (sm_103a FFMA2 path; ptxas won't auto-fuse) ----
__device__ __forceinline__ ull ffma2(ull a, ull b, ull c) {
    ull d;
    asm("fma.rn.f32x2 %0, %1, %2, %3;" : "=l"(d) : "l"(a), "l"(b), "l"(c));
    return d;
}
__device__ __forceinline__ ull fmul2(ull a, ull b) {
    ull d;
    asm("mul.rn.f32x2 %0, %1, %2;" : "=l"(d) : "l"(a), "l"(b));
    return d;
}
__device__ __forceinline__ ull pack2(float lo, float hi) {
    ull d;
    asm("mov.b64 %0, {%1, %2};" : "=l"(d) : "f"(lo), "f"(hi));
    return d;
}
__device__ __forceinline__ float2 unpack2(ull v) {
    float2 r;
    asm("mov.b64 {%0, %1}, %2;" : "=f"(r.x), "=f"(r.y) : "l"(v));
    return r;
}

// Scratch (allocation-free rule: __device__ globals)
__device__ float g_Q[B_DIM * H_DIM * T_DIM * D_DIM];   // [B,H,T,d], pre-scaled
__device__ float g_K[B_DIM * H_DIM * T_DIM * D_DIM];
__device__ float g_V[B_DIM * H_DIM * T_DIM * D_DIM];
__device__ float g_ctx[M_DIM * E_DIM];                 // [T,B,E]

// ---------------------------------------------------------------------------
// Tiled GEMM: C[m,f] = sum_e A[m,e] * W[f,e] + bias[f]
// Block tile 128x128, K-tile 16, 256 threads, 8x8 per thread (f32x2 packed).
// ---------------------------------------------------------------------------
#define BM 128
#define BN 128
#define BK 16
#define TM 8
#define TN 8

__global__ __launch_bounds__(256, 2)
void gemm_qkv_kernel(const float* __restrict__ A,
                     const float* __restrict__ W,
                     const float* __restrict__ bias) {
    __shared__ float As[BK][BM];
    __shared__ float Ws[BK][BN];

    const int bm = blockIdx.y * BM;
    const int bn = blockIdx.x * BN;
    const int tid = threadIdx.x;
    const int ty = tid >> 4;       // 0..15 (M direction)
    const int tx = tid & 15;       // 0..15 (N direction)

    ull acc2[TM][TN / 2];
#pragma unroll
    for (int i = 0; i < TM; i++)
#pragma unroll
        for (int j = 0; j < TN / 2; j++) acc2[i][j] = 0ull;

    for (int k0 = 0; k0 < E_DIM; k0 += BK) {
#pragma unroll
        for (int i = tid; i < BM * BK / 4; i += 256) {
            int row = i >> 2;
            int kq  = (i & 3) << 2;
            float4 v = *(const float4*)(A + (size_t)(bm + row) * E_DIM + k0 + kq);
            As[kq + 0][row] = v.x; As[kq + 1][row] = v.y;
            As[kq + 2][row] = v.z; As[kq + 3][row] = v.w;
        }
#pragma unroll
        for (int i = tid; i < BN * BK / 4; i += 256) {
            int row = i >> 2;
            int kq  = (i & 3) << 2;
            float4 v = *(const float4*)(W + (size_t)(bn + row) * E_DIM + k0 + kq);
            Ws[kq + 0][row] = v.x; Ws[kq + 1][row] = v.y;
            Ws[kq + 2][row] = v.z; Ws[kq + 3][row] = v.w;
        }
        __syncthreads();

#pragma unroll
        for (int kk = 0; kk < BK; kk++) {
            // a: 8 scalars, replicated into packed pairs (mov.b64 -> ALU pipe)
            float4 a0 = *(const float4*)&As[kk][ty * TM + 0];
            float4 a1 = *(const float4*)&As[kk][ty * TM + 4];
            ull a2[TM];
            a2[0] = pack2(a0.x, a0.x); a2[1] = pack2(a0.y, a0.y);
            a2[2] = pack2(a0.z, a0.z); a2[3] = pack2(a0.w, a0.w);
            a2[4] = pack2(a1.x, a1.x); a2[5] = pack2(a1.y, a1.y);
            a2[6] = pack2(a1.z, a1.z); a2[7] = pack2(a1.w, a1.w);
            // b: 8 floats = 4 adjacent pairs, loaded packed directly
            ulonglong2 bb0 = *(const ulonglong2*)&Ws[kk][tx * TN + 0];
            ulonglong2 bb1 = *(const ulonglong2*)&Ws[kk][tx * TN + 4];
            ull b2[TN / 2] = {bb0.x, bb0.y, bb1.x, bb1.y};
#pragma unroll
            for (int i = 0; i < TM; i++)
#pragma unroll
                for (int j = 0; j < TN / 2; j++)
                    acc2[i][j] = ffma2(a2[i], b2[j], acc2[i][j]);
        }
        __syncthreads();
    }

    // Epilogue: add bias, scale q, scatter to g_Q/g_K/g_V in [B,H,T,d]
#pragma unroll
    for (int i = 0; i < TM; i++) {
        int m = bm + ty * TM + i;
        int t = m >> 1;          // B_DIM == 2
        int b = m & 1;
#pragma unroll
        for (int j2 = 0; j2 < TN / 2; j2++) {
            float2 av = unpack2(acc2[i][j2]);
#pragma unroll
            for (int u = 0; u < 2; u++) {
                int f = bn + tx * TN + 2 * j2 + u;
                float v = (u == 0 ? av.x : av.y) + bias[f];
                int h  = f / (3 * D_DIM);
                int r  = f - h * (3 * D_DIM);
                int jj = r >> 6;             // D_DIM == 64
                int dd = r & 63;
                size_t idx = (((size_t)(b * H_DIM + h)) * T_DIM + t) * D_DIM + dd;
                if (jj == 0)      g_Q[idx] = v * 0.125f;   // 1/sqrt(64)
                else if (jj == 1) g_K[idx] = v;
                else              g_V[idx] = v;
            }
        }
    }
}

__global__ __launch_bounds__(256, 2)
void gemm_out_kernel(const float* __restrict__ W,
                     const float* __restrict__ bias,
                     float* __restrict__ out) {
    __shared__ float As[BK][BM];
    __shared__ float Ws[BK][BN];

    const int bm = blockIdx.y * BM;
    const int bn = blockIdx.x * BN;
    const int tid = threadIdx.x;
    const int ty = tid >> 4;
    const int tx = tid & 15;

    ull acc2[TM][TN / 2];
#pragma unroll
    for (int i = 0; i < TM; i++)
#pragma unroll
        for (int j = 0; j < TN / 2; j++) acc2[i][j] = 0ull;

    for (int k0 = 0; k0 < E_DIM; k0 += BK) {
#pragma unroll
        for (int i = tid; i < BM * BK / 4; i += 256) {
            int row = i >> 2;
            int kq  = (i & 3) << 2;
            float4 v = *(const float4*)(g_ctx + (size_t)(bm + row) * E_DIM + k0 + kq);
            As[kq + 0][row] = v.x; As[kq + 1][row] = v.y;
            As[kq + 2][row] = v.z; As[kq + 3][row] = v.w;
        }
#pragma unroll
        for (int i = tid; i < BN * BK / 4; i += 256) {
            int row = i >> 2;
            int kq  = (i & 3) << 2;
            float4 v = *(const float4*)(W + (size_t)(bn + row) * E_DIM + k0 + kq);
            Ws[kq + 0][row] = v.x; Ws[kq + 1][row] = v.y;
            Ws[kq + 2][row] = v.z; Ws[kq + 3][row] = v.w;
        }
        __syncthreads();

#pragma unroll
        for (int kk = 0; kk < BK; kk++) {
            float4 a0 = *(const float4*)&As[kk][ty * TM + 0];
            float4 a1 = *(const float4*)&As[kk][ty * TM + 4];
            ull a2[TM];
            a2[0] = pack2(a0.x, a0.x); a2[1] = pack2(a0.y, a0.y);
            a2[2] = pack2(a0.z, a0.z); a2[3] = pack2(a0.w, a0.w);
            a2[4] = pack2(a1.x, a1.x); a2[5] = pack2(a1.y, a1.y);
            a2[6] = pack2(a1.z, a1.z); a2[7] = pack2(a1.w, a1.w);
            ulonglong2 bb0 = *(const ulonglong2*)&Ws[kk][tx * TN + 0];
            ulonglong2 bb1 = *(const ulonglong2*)&Ws[kk][tx * TN + 4];
            ull b2[TN / 2] = {bb0.x, bb0.y, bb1.x, bb1.y};
#pragma unroll
            for (int i = 0; i < TM; i++)
#pragma unroll
                for (int j = 0; j < TN / 2; j++)
                    acc2[i][j] = ffma2(a2[i], b2[j], acc2[i][j]);
        }
        __syncthreads();
    }

#pragma unroll
    for (int i = 0; i < TM; i++) {
        int m = bm + ty * TM + i;
#pragma unroll
        for (int j2 = 0; j2 < TN / 2; j2++) {
            float2 av = unpack2(acc2[i][j2]);
            int f = bn + tx * TN + 2 * j2;
            out[(size_t)m * E_DIM + f + 0] = av.x + bias[f + 0];
            out[(size_t)m * E_DIM + f + 1] = av.y + bias[f + 1];
        }
    }
}

// ---------------------------------------------------------------------------
// Flash-attention: one thread per query row. q and acc held as packed f32x2
// register pairs; K/V streamed through smem in 32-row tiles; online softmax.
// Grid: (T/128, B*H), 128 threads.
// ---------------------------------------------------------------------------
#define AT_BM 128
#define AT_BN 32

__global__ __launch_bounds__(128, 2)
void attn_kernel() {
    __shared__ float Ks[AT_BN][D_DIM];
    __shared__ float Vs[AT_BN][D_DIM];

    const int bh = blockIdx.y;                 // 0..31: b*H + h
    const int q0 = blockIdx.x * AT_BM;
    const int tid = threadIdx.x;

    const float* __restrict__ Qg = g_Q + (size_t)bh * T_DIM * D_DIM;
    const float* __restrict__ Kg = g_K + (size_t)bh * T_DIM * D_DIM;
    const float* __restrict__ Vg = g_V + (size_t)bh * T_DIM * D_DIM;

    // q and acc as 32 packed pairs each (adjacent d components)
    ull q2[D_DIM / 2], acc2[D_DIM / 2];
    {
        const ulonglong2* qr = (const ulonglong2*)(Qg + (size_t)(q0 + tid) * D_DIM);
#pragma unroll
        for (int i = 0; i < D_DIM / 4; i++) {
            ulonglong2 v = qr[i];
            q2[2 * i + 0] = v.x;
            q2[2 * i + 1] = v.y;
        }
    }
#pragma unroll
    for (int i = 0; i < D_DIM / 2; i++) acc2[i] = 0ull;

    float mrun = -INFINITY;
    float lrun = 0.0f;

    for (int s0 = 0; s0 < T_DIM; s0 += AT_BN) {
        __syncthreads();
#pragma unroll
        for (int i = tid; i < AT_BN * D_DIM / 4; i += 128) {
            ((float4*)Ks)[i] = ((const float4*)(Kg + (size_t)s0 * D_DIM))[i];
            ((float4*)Vs)[i] = ((const float4*)(Vg + (size_t)s0 * D_DIM))[i];
        }
        __syncthreads();

        // scores: packed accumulation over d, horizontal add at the end
        float s[AT_BN];
#pragma unroll
        for (int j = 0; j < AT_BN; j++) {
            ull sa = 0ull, sb = 0ull;   // two chains to cut RAW depth
#pragma unroll
            for (int kq = 0; kq < D_DIM / 4; kq++) {
                ulonglong2 kv = *(const ulonglong2*)&Ks[j][4 * kq];
                sa = ffma2(q2[2 * kq + 0], kv.x, sa);
                sb = ffma2(q2[2 * kq + 1], kv.y, sb);
            }
            float2 fa = unpack2(sa);
            float2 fb = unpack2(sb);
            s[j] = (fa.x + fb.x) + (fa.y + fb.y);
        }

        // online softmax (scalar fp32, MUFU)
        float mt = s[0];
#pragma unroll
        for (int j = 1; j < AT_BN; j++) mt = fmaxf(mt, s[j]);
        float mnew = fmaxf(mrun, mt);
        float scale = __expf(mrun - mnew);     // 0 on the first tile
        float p[AT_BN];
        float lsum = 0.0f;
#pragma unroll
        for (int j = 0; j < AT_BN; j++) {
            p[j] = __expf(s[j] - mnew);
            lsum += p[j];
        }
        lrun = lrun * scale + lsum;
        ull scale2 = pack2(scale, scale);
#pragma unroll
        for (int i = 0; i < D_DIM / 2; i++) acc2[i] = fmul2(acc2[i], scale2);

        // acc += P @ V (packed over d)
#pragma unroll
        for (int j = 0; j < AT_BN; j++) {
            ull p2 = pack2(p[j], p[j]);
#pragma unroll
            for (int i2 = 0; i2 < D_DIM / 4; i2++) {
                ulonglong2 vv = *(const ulonglong2*)&Vs[j][4 * i2];
                acc2[2 * i2 + 0] = ffma2(p2, vv.x, acc2[2 * i2 + 0]);
                acc2[2 * i2 + 1] = ffma2(p2, vv.y, acc2[2 * i2 + 1]);
            }
        }
        mrun = mnew;
    }

    // normalize and write ctx as [T,B,E] with E index = h*64 + dd
    const int b = bh >> 4;           // H_DIM == 16
    const int h = bh & 15;
    const int t = q0 + tid;
    float inv_l = 1.0f / lrun;
    ull inv2 = pack2(inv_l, inv_l);
    float* dst = g_ctx + ((size_t)t * B_DIM + b) * E_DIM + h * D_DIM;
#pragma unroll
    for (int i2 = 0; i2 < D_DIM / 4; i2++) {
        ulonglong2 v;
        v.x = fmul2(acc2[2 * i2 + 0], inv2);
        v.y = fmul2(acc2[2 * i2 + 1], inv2);
        *(ulonglong2*)(dst + 4 * i2) = v;
    }
}

// ---------------------------------------------------------------------------
extern "C" void kernel_launch(void* const* d_in, const int* in_sizes, int n_in,
                              void* d_out, int out_size) {
    const float* query = (const float*)d_in[0];   // (T,B,E)
    const float* w_in  = (const float*)d_in[1];   // (3E,E)
    const float* b_in  = (const float*)d_in[2];   // (3E,)
    const float* w_out = (const float*)d_in[3];   // (E,E)
    const float* b_out = (const float*)d_in[4];   // (E,)
    float* out = (float*)d_out;                   // (T,B,E)

    dim3 g1(3 * E_DIM / BN, M_DIM / BM);          // 24 x 32
    gemm_qkv_kernel<<<g1, 256>>>(query, w_in, b_in);

    dim3 g2(T_DIM / AT_BM, B_DIM * H_DIM);        // 16 x 32
    attn_kernel<<<g2, 128>>>();

    dim3 g3(E_DIM / BN, M_DIM / BM);              // 8 x 32
    gemm_out_kernel<<<g3, 256>>>(w_out, b_out, out);
}

// round 14
// speedup vs baseline: 1.3865x; 1.3165x over previous
#include <cuda_runtime.h>
#include <cuda_bf16.h>
#include <cstdint>
#include <math.h>

// Fixed problem shapes
#define T_DIM 2048
#define B_DIM 2
#define E_DIM 1024
#define H_DIM 16
#define D_DIM 64
#define M_DIM (T_DIM * B_DIM)   // 4096 rows for projections

typedef unsigned long long ull;

// ---- packed f32x2 helpers (attention) ----
__device__ __forceinline__ ull ffma2(ull a, ull b, ull c) {
    ull d;
    asm("fma.rn.f32x2 %0, %1, %2, %3;" : "=l"(d) : "l"(a), "l"(b), "l"(c));
    return d;
}
__device__ __forceinline__ ull fmul2(ull a, ull b) {
    ull d;
    asm("mul.rn.f32x2 %0, %1, %2;" : "=l"(d) : "l"(a), "l"(b));
    return d;
}
__device__ __forceinline__ ull pack2(float lo, float hi) {
    ull d;
    asm("mov.b64 %0, {%1, %2};" : "=l"(d) : "f"(lo), "f"(hi));
    return d;
}
__device__ __forceinline__ float2 unpack2(ull v) {
    float2 r;
    asm("mov.b64 {%0, %1}, %2;" : "=f"(r.x), "=f"(r.y) : "l"(v));
    return r;
}

__device__ __forceinline__ uint32_t smem_u32(const void* p) {
    uint32_t a;
    asm("{ .reg .u64 t; cvta.to.shared.u64 t, %1; cvt.u32.u64 %0, t; }"
        : "=r"(a) : "l"(p));
    return a;
}

// ---- portable tensor-core primitives (no 'a'-suffix features) -------------
__device__ __forceinline__ void ldsm_x4(uint32_t r[4], uint32_t addr) {
    asm volatile("ldmatrix.sync.aligned.m8n8.x4.shared.b16 {%0,%1,%2,%3}, [%4];"
                 : "=r"(r[0]), "=r"(r[1]), "=r"(r[2]), "=r"(r[3]) : "r"(addr));
}
__device__ __forceinline__ void mma16816(float c[4], const uint32_t a[4],
                                         uint32_t b0, uint32_t b1) {
    asm volatile(
        "mma.sync.aligned.m16n8k16.row.col.f32.bf16.bf16.f32 "
        "{%0,%1,%2,%3}, {%4,%5,%6,%7}, {%8,%9}, {%0,%1,%2,%3};"
        : "+f"(c[0]), "+f"(c[1]), "+f"(c[2]), "+f"(c[3])
        : "r"(a[0]), "r"(a[1]), "r"(a[2]), "r"(a[3]), "r"(b0), "r"(b1));
}
__device__ __forceinline__ void cp_async16(uint32_t saddr, const void* gaddr) {
    asm volatile("cp.async.cg.shared.global [%0], [%1], 16;"
                 :: "r"(saddr), "l"(gaddr));
}
#define CP_COMMIT() asm volatile("cp.async.commit_group;" ::: "memory")
#define CP_WAIT0()  asm volatile("cp.async.wait_group 0;" ::: "memory")
#define CP_WAIT1()  asm volatile("cp.async.wait_group 1;" ::: "memory")

// ---- scratch (__device__ globals; allocation-free rule) -------------------
__device__ float g_Q[B_DIM * H_DIM * T_DIM * D_DIM];   // [B,H,T,d], pre-scaled
__device__ float g_K[B_DIM * H_DIM * T_DIM * D_DIM];
__device__ float g_V[B_DIM * H_DIM * T_DIM * D_DIM];

__device__ __nv_bfloat16 g_qh[M_DIM * E_DIM],  g_ql[M_DIM * E_DIM];
__device__ __nv_bfloat16 g_wih[3 * E_DIM * E_DIM], g_wil[3 * E_DIM * E_DIM];
__device__ __nv_bfloat16 g_woh[E_DIM * E_DIM], g_wol[E_DIM * E_DIM];
__device__ __nv_bfloat16 g_cth[M_DIM * E_DIM], g_ctl[M_DIM * E_DIM];

// ---------------------------------------------------------------------------
// Split fp32 -> bf16 hi + bf16 lo
// ---------------------------------------------------------------------------
__global__ void split_kernel(const float* __restrict__ src,
                             __nv_bfloat16* __restrict__ h,
                             __nv_bfloat16* __restrict__ l, int n) {
    int i = blockIdx.x * 256 + threadIdx.x;
    if (i < n) {
        float x = src[i];
        __nv_bfloat16 hh = __float2bfloat16(x);
        h[i] = hh;
        l[i] = __float2bfloat16(x - __bfloat162float(hh));
    }
}

// ---------------------------------------------------------------------------
// mma.sync GEMM: C[m,f] = sum_e A[m,e]*W[f,e] + bias[f]
// bf16 3-term split, fp32 accumulators. CTA 128x128, 8 warps (warp 32x64),
// K-chunk 32, cp.async double-buffered smem with padded pitch.
// MODE 0: QKV scatter epilogue. MODE 1: plain store.
// ---------------------------------------------------------------------------
#define KC 32
#define PITCH 40                                   // bf16 elements (80B rows)
#define TILE_ELEMS (128 * PITCH)
#define BUF_ELEMS (4 * TILE_ELEMS)                 // Ah, Al, Wh, Wl
#define BUF_BYTES (BUF_ELEMS * 2)                  // 40960
#define GEMM_SMEM (2 * BUF_BYTES)                  // 81920
#define NCHUNK (E_DIM / KC)                        // 32

template <int MODE>
__global__ __launch_bounds__(256)
void mma_gemm_kernel(const __nv_bfloat16* __restrict__ Ah,
                     const __nv_bfloat16* __restrict__ Al,
                     const __nv_bfloat16* __restrict__ Wh,
                     const __nv_bfloat16* __restrict__ Wl,
                     const float* __restrict__ bias,
                     float* __restrict__ outp) {
    extern __shared__ __align__(128) char dsm[];
    const uint32_t sbase = smem_u32(dsm);
    const int tid  = threadIdx.x;
    const int wid  = tid >> 5;
    const int lane = tid & 31;
    const int bm = blockIdx.y * 128;
    const int bn = blockIdx.x * 128;
    const int wm = (wid & 3) * 32;          // warp m-offset in tile
    const int wn = (wid >> 2) * 64;         // warp n-offset in tile

    float acc[2][8][4];
#pragma unroll
    for (int i = 0; i < 2; i++)
#pragma unroll
        for (int j = 0; j < 8; j++)
#pragma unroll
            for (int u = 0; u < 4; u++) acc[i][j][u] = 0.0f;

    // chunk loader: 4 tiles of 128 rows x 32 bf16 (64B) each, cp.async 16B
    auto load_chunk = [&](int c, int b) {
        const int k0 = c * KC;
        const uint32_t bufb = sbase + b * BUF_BYTES;
        auto one = [&](const __nv_bfloat16* __restrict__ src, int row0, int toff) {
#pragma unroll
            for (int it = 0; it < 2; it++) {
                int unit = tid + it * 256;          // 0..511
                int row = unit >> 2;
                int q   = unit & 3;
                const void* g = src + (size_t)(row0 + row) * E_DIM + k0 + q * 8;
                uint32_t s = bufb + (uint32_t)(toff + row * PITCH + q * 8) * 2;
                cp_async16(s, g);
            }
        };
        one(Ah, bm, 0);
        one(Al, bm, TILE_ELEMS);
        one(Wh, bn, 2 * TILE_ELEMS);
        one(Wl, bn, 3 * TILE_ELEMS);
        CP_COMMIT();
    };

    load_chunk(0, 0);

    for (int c = 0; c < NCHUNK; c++) {
        const int b = c & 1;
        if (c + 1 < NCHUNK) { load_chunk(c + 1, b ^ 1); CP_WAIT1(); }
        else                { CP_WAIT0(); }
        __syncthreads();

        const uint32_t bufb = sbase + b * BUF_BYTES;
        const uint32_t aAh = bufb;
        const uint32_t aAl = bufb + TILE_ELEMS * 2;
        const uint32_t aWh = bufb + 2 * TILE_ELEMS * 2;
        const uint32_t aWl = bufb + 3 * TILE_ELEMS * 2;
        const int lrow = lane & 15;
        const int lk8  = (lane >> 4) * 8;

#pragma unroll
        for (int k16 = 0; k16 < KC / 16; k16++) {
            const int koff = k16 * 16 + lk8;
            uint32_t ah[2][4], al[2][4];
#pragma unroll
            for (int ma = 0; ma < 2; ma++) {
                uint32_t ro = (uint32_t)((wm + ma * 16 + lrow) * PITCH + koff) * 2;
                ldsm_x4(ah[ma], aAh + ro);
                ldsm_x4(al[ma], aAl + ro);
            }
#pragma unroll
            for (int ng = 0; ng < 4; ng++) {
                uint32_t ro = (uint32_t)((wn + ng * 16 + lrow) * PITCH + koff) * 2;
                uint32_t bh[4], bl[4];
                ldsm_x4(bh, aWh + ro);
                ldsm_x4(bl, aWl + ro);
#pragma unroll
                for (int ma = 0; ma < 2; ma++) {
                    // n-atom 2*ng   -> frags {r0, r2}
                    mma16816(acc[ma][2 * ng],     ah[ma], bh[0], bh[2]);
                    mma16816(acc[ma][2 * ng],     ah[ma], bl[0], bl[2]);
                    mma16816(acc[ma][2 * ng],     al[ma], bh[0], bh[2]);
                    // n-atom 2*ng+1 -> frags {r1, r3}
                    mma16816(acc[ma][2 * ng + 1], ah[ma], bh[1], bh[3]);
                    mma16816(acc[ma][2 * ng + 1], ah[ma], bl[1], bl[3]);
                    mma16816(acc[ma][2 * ng + 1], al[ma], bh[1], bh[3]);
                }
            }
        }
        __syncthreads();
    }

    // Epilogue. C atom m16n8: c0 @ (row=lane>>2, col=2*(lane&3)), c1 col+1,
    // c2/c3 at row+8.
    const int r0 = lane >> 2;
    const int c0 = (lane & 3) * 2;
#pragma unroll
    for (int ma = 0; ma < 2; ma++) {
#pragma unroll
        for (int na = 0; na < 8; na++) {
#pragma unroll
            for (int half = 0; half < 2; half++) {
                const int m = bm + wm + ma * 16 + r0 + half * 8;
                const int f = bn + wn + na * 8 + c0;
                const float v0 = acc[ma][na][2 * half + 0] + __ldg(&bias[f]);
                const float v1 = acc[ma][na][2 * half + 1] + __ldg(&bias[f + 1]);
                if (MODE == 1) {
                    *(float2*)(outp + (size_t)m * E_DIM + f) = make_float2(v0, v1);
                } else {
                    const int t = m >> 1;
                    const int bb = m & 1;
#pragma unroll
                    for (int u = 0; u < 2; u++) {
                        const int ff = f + u;
                        const float v = (u == 0) ? v0 : v1;
                        const int h  = ff / (3 * D_DIM);
                        const int r  = ff - h * (3 * D_DIM);
                        const int jj = r >> 6;
                        const int dd = r & 63;
                        const size_t idx =
                            (((size_t)(bb * H_DIM + h)) * T_DIM + t) * D_DIM + dd;
                        if (jj == 0)      g_Q[idx] = v * 0.125f;   // 1/sqrt(64)
                        else if (jj == 1) g_K[idx] = v;
                        else              g_V[idx] = v;
                    }
                }
            }
        }
    }
}

// ---------------------------------------------------------------------------
// Flash-attention (fp32 SIMT, passing R9 version); emits bf16 hi/lo ctx.
// Grid: (T/128, B*H), 128 threads.
// ---------------------------------------------------------------------------
#define AT_BM 128
#define AT_BN 32

__global__ __launch_bounds__(128, 2)
void attn_kernel() {
    __shared__ float Ks[AT_BN][D_DIM];
    __shared__ float Vs[AT_BN][D_DIM];

    const int bh = blockIdx.y;
    const int q0 = blockIdx.x * AT_BM;
    const int tid = threadIdx.x;

    const float* __restrict__ Qg = g_Q + (size_t)bh * T_DIM * D_DIM;
    const float* __restrict__ Kg = g_K + (size_t)bh * T_DIM * D_DIM;
    const float* __restrict__ Vg = g_V + (size_t)bh * T_DIM * D_DIM;

    ull q2[D_DIM / 2], acc2[D_DIM / 2];
    {
        const ulonglong2* qr = (const ulonglong2*)(Qg + (size_t)(q0 + tid) * D_DIM);
#pragma unroll
        for (int i = 0; i < D_DIM / 4; i++) {
            ulonglong2 v = qr[i];
            q2[2 * i + 0] = v.x;
            q2[2 * i + 1] = v.y;
        }
    }
#pragma unroll
    for (int i = 0; i < D_DIM / 2; i++) acc2[i] = 0ull;

    float mrun = -INFINITY;
    float lrun = 0.0f;

    for (int s0 = 0; s0 < T_DIM; s0 += AT_BN) {
        __syncthreads();
#pragma unroll
        for (int i = tid; i < AT_BN * D_DIM / 4; i += 128) {
            ((float4*)Ks)[i] = ((const float4*)(Kg + (size_t)s0 * D_DIM))[i];
            ((float4*)Vs)[i] = ((const float4*)(Vg + (size_t)s0 * D_DIM))[i];
        }
        __syncthreads();

        float s[AT_BN];
#pragma unroll
        for (int j = 0; j < AT_BN; j++) {
            ull sa = 0ull, sb = 0ull;
#pragma unroll
            for (int kq = 0; kq < D_DIM / 4; kq++) {
                ulonglong2 kv = *(const ulonglong2*)&Ks[j][4 * kq];
                sa = ffma2(q2[2 * kq + 0], kv.x, sa);
                sb = ffma2(q2[2 * kq + 1], kv.y, sb);
            }
            float2 fa = unpack2(sa);
            float2 fb = unpack2(sb);
            s[j] = (fa.x + fb.x) + (fa.y + fb.y);
        }

        float mt = s[0];
#pragma unroll
        for (int j = 1; j < AT_BN; j++) mt = fmaxf(mt, s[j]);
        float mnew = fmaxf(mrun, mt);
        float scale = __expf(mrun - mnew);
        float p[AT_BN];
        float lsum = 0.0f;
#pragma unroll
        for (int j = 0; j < AT_BN; j++) {
            p[j] = __expf(s[j] - mnew);
            lsum += p[j];
        }
        lrun = lrun * scale + lsum;
        ull scale2 = pack2(scale, scale);
#pragma unroll
        for (int i = 0; i < D_DIM / 2; i++) acc2[i] = fmul2(acc2[i], scale2);

#pragma unroll
        for (int j = 0; j < AT_BN; j++) {
            ull p2 = pack2(p[j], p[j]);
#pragma unroll
            for (int i2 = 0; i2 < D_DIM / 4; i2++) {
                ulonglong2 vv = *(const ulonglong2*)&Vs[j][4 * i2];
                acc2[2 * i2 + 0] = ffma2(p2, vv.x, acc2[2 * i2 + 0]);
                acc2[2 * i2 + 1] = ffma2(p2, vv.y, acc2[2 * i2 + 1]);
            }
        }
        mrun = mnew;
    }

    const int b = bh >> 4;
    const int h = bh & 15;
    const int t = q0 + tid;
    const float inv_l = 1.0f / lrun;
    const size_t base = ((size_t)t * B_DIM + b) * E_DIM + h * D_DIM;
    __nv_bfloat162* dh = (__nv_bfloat162*)(g_cth + base);
    __nv_bfloat162* dl = (__nv_bfloat162*)(g_ctl + base);
#pragma unroll
    for (int i2 = 0; i2 < D_DIM / 2; i2++) {
        float2 av = unpack2(acc2[i2]);
        float vx = av.x * inv_l, vy = av.y * inv_l;
        __nv_bfloat16 hx = __float2bfloat16(vx), hy = __float2bfloat16(vy);
        __nv_bfloat16 lx = __float2bfloat16(vx - __bfloat162float(hx));
        __nv_bfloat16 ly = __float2bfloat16(vy - __bfloat162float(hy));
        dh[i2] = __nv_bfloat162{hx, hy};
        dl[i2] = __nv_bfloat162{lx, ly};
    }
}

// ---------------------------------------------------------------------------
extern "C" void kernel_launch(void* const* d_in, const int* in_sizes, int n_in,
                              void* d_out, int out_size) {
    const float* query = (const float*)d_in[0];   // (T,B,E)
    const float* w_in  = (const float*)d_in[1];   // (3E,E)
    const float* b_in  = (const float*)d_in[2];   // (3E,)
    const float* w_out = (const float*)d_in[3];   // (E,E)
    const float* b_out = (const float*)d_in[4];   // (E,)
    float* out = (float*)d_out;                   // (T,B,E)

    cudaFuncSetAttribute(mma_gemm_kernel<0>,
                         cudaFuncAttributeMaxDynamicSharedMemorySize, GEMM_SMEM);
    cudaFuncSetAttribute(mma_gemm_kernel<1>,
                         cudaFuncAttributeMaxDynamicSharedMemorySize, GEMM_SMEM);

    __nv_bfloat16 *qh, *ql, *wih, *wil, *woh, *wol, *cth, *ctl;
    cudaGetSymbolAddress((void**)&qh,  g_qh);
    cudaGetSymbolAddress((void**)&ql,  g_ql);
    cudaGetSymbolAddress((void**)&wih, g_wih);
    cudaGetSymbolAddress((void**)&wil, g_wil);
    cudaGetSymbolAddress((void**)&woh, g_woh);
    cudaGetSymbolAddress((void**)&wol, g_wol);
    cudaGetSymbolAddress((void**)&cth, g_cth);
    cudaGetSymbolAddress((void**)&ctl, g_ctl);

    // 1) bf16 hi/lo splits
    {
        int n = M_DIM * E_DIM;
        split_kernel<<<(n + 255) / 256, 256>>>(query, qh, ql, n);
        n = 3 * E_DIM * E_DIM;
        split_kernel<<<(n + 255) / 256, 256>>>(w_in, wih, wil, n);
        n = E_DIM * E_DIM;
        split_kernel<<<(n + 255) / 256, 256>>>(w_out, woh, wol, n);
    }

    // 2) QKV projection on tensor cores (mma.sync), scatter epilogue
    {
        dim3 g(3 * E_DIM / 128, M_DIM / 128);   // 24 x 32
        mma_gemm_kernel<0><<<g, 256, GEMM_SMEM>>>(qh, ql, wih, wil, b_in, nullptr);
    }

    // 3) attention (fp32 SIMT), emits split ctx
    {
        dim3 g(T_DIM / AT_BM, B_DIM * H_DIM);   // 16 x 32
        attn_kernel<<<g, 128>>>();
    }

    // 4) output projection on tensor cores
    {
        dim3 g(E_DIM / 128, M_DIM / 128);       // 8 x 32
        mma_gemm_kernel<1><<<g, 256, GEMM_SMEM>>>(cth, ctl, woh, wol, b_out, out);
    }
}

// round 15
// speedup vs baseline: 2.7765x; 2.0025x over previous
#include <cuda_runtime.h>
#include <cuda_bf16.h>
#include <cstdint>
#include <math.h>

// Fixed problem shapes
#define T_DIM 2048
#define B_DIM 2
#define E_DIM 1024
#define H_DIM 16
#define D_DIM 64
#define M_DIM (T_DIM * B_DIM)   // 4096 rows for projections

__device__ __forceinline__ uint32_t smem_u32(const void* p) {
    uint32_t a;
    asm("{ .reg .u64 t; cvta.to.shared.u64 t, %1; cvt.u32.u64 %0, t; }"
        : "=r"(a) : "l"(p));
    return a;
}

// ---- portable tensor-core primitives (no 'a'-suffix features) -------------
__device__ __forceinline__ void ldsm_x4(uint32_t r[4], uint32_t addr) {
    asm volatile("ldmatrix.sync.aligned.m8n8.x4.shared.b16 {%0,%1,%2,%3}, [%4];"
                 : "=r"(r[0]), "=r"(r[1]), "=r"(r[2]), "=r"(r[3]) : "r"(addr));
}
__device__ __forceinline__ void mma16816(float c[4], const uint32_t a[4],
                                         uint32_t b0, uint32_t b1) {
    asm volatile(
        "mma.sync.aligned.m16n8k16.row.col.f32.bf16.bf16.f32 "
        "{%0,%1,%2,%3}, {%4,%5,%6,%7}, {%8,%9}, {%0,%1,%2,%3};"
        : "+f"(c[0]), "+f"(c[1]), "+f"(c[2]), "+f"(c[3])
        : "r"(a[0]), "r"(a[1]), "r"(a[2]), "r"(a[3]), "r"(b0), "r"(b1));
}
__device__ __forceinline__ void cp_async16(uint32_t saddr, const void* gaddr) {
    asm volatile("cp.async.cg.shared.global [%0], [%1], 16;"
                 :: "r"(saddr), "l"(gaddr));
}
#define CP_COMMIT() asm volatile("cp.async.commit_group;" ::: "memory")
#define CP_WAIT0()  asm volatile("cp.async.wait_group 0;" ::: "memory")
#define CP_WAIT1()  asm volatile("cp.async.wait_group 1;" ::: "memory")

// bf16x2 pack / hi-lo split helpers
__device__ __forceinline__ uint32_t pack_bf16x2(float x, float y) {
    __nv_bfloat162 t = __float22bfloat162_rn(make_float2(x, y));
    return *reinterpret_cast<uint32_t*>(&t);
}
__device__ __forceinline__ void split2(float x, float y, uint32_t& h, uint32_t& l) {
    __nv_bfloat162 hb = __float22bfloat162_rn(make_float2(x, y));
    float2 hf = __bfloat1622float2(hb);
    __nv_bfloat162 lb = __float22bfloat162_rn(make_float2(x - hf.x, y - hf.y));
    h = *reinterpret_cast<uint32_t*>(&hb);
    l = *reinterpret_cast<uint32_t*>(&lb);
}

// ---- scratch (__device__ globals; allocation-free rule) -------------------
__device__ __nv_bfloat16 g_Qh[32 * T_DIM * D_DIM], g_Ql[32 * T_DIM * D_DIM]; // [bh][t][d]
__device__ __nv_bfloat16 g_Kh[32 * T_DIM * D_DIM], g_Kl[32 * T_DIM * D_DIM]; // [bh][t][d]
__device__ __nv_bfloat16 g_Vh[32 * D_DIM * T_DIM], g_Vl[32 * D_DIM * T_DIM]; // [bh][d][t]

__device__ __nv_bfloat16 g_qh[M_DIM * E_DIM],  g_ql[M_DIM * E_DIM];
__device__ __nv_bfloat16 g_wih[3 * E_DIM * E_DIM], g_wil[3 * E_DIM * E_DIM];
__device__ __nv_bfloat16 g_woh[E_DIM * E_DIM], g_wol[E_DIM * E_DIM];
__device__ __nv_bfloat16 g_cth[M_DIM * E_DIM], g_ctl[M_DIM * E_DIM];

// ---------------------------------------------------------------------------
// Split fp32 -> bf16 hi + bf16 lo
// ---------------------------------------------------------------------------
__global__ void split_kernel(const float* __restrict__ src,
                             __nv_bfloat16* __restrict__ h,
                             __nv_bfloat16* __restrict__ l, int n) {
    int i = blockIdx.x * 256 + threadIdx.x;
    if (i < n) {
        float x = src[i];
        __nv_bfloat16 hh = __float2bfloat16(x);
        h[i] = hh;
        l[i] = __float2bfloat16(x - __bfloat162float(hh));
    }
}

// ---------------------------------------------------------------------------
// mma.sync GEMM: C[m,f] = sum_e A[m,e]*W[f,e] + bias[f]
// bf16 3-term split, fp32 accum. CTA 128x128, 8 warps, K-chunk 32, cp.async
// double-buffered. MODE 0: QKV split-scatter epilogue. MODE 1: plain store.
// ---------------------------------------------------------------------------
#define KC 32
#define PITCH 40
#define TILE_ELEMS (128 * PITCH)
#define BUF_ELEMS (4 * TILE_ELEMS)
#define BUF_BYTES (BUF_ELEMS * 2)
#define GEMM_SMEM (2 * BUF_BYTES)
#define NCHUNK (E_DIM / KC)

template <int MODE>
__global__ __launch_bounds__(256, 2)
void mma_gemm_kernel(const __nv_bfloat16* __restrict__ Ah,
                     const __nv_bfloat16* __restrict__ Al,
                     const __nv_bfloat16* __restrict__ Wh,
                     const __nv_bfloat16* __restrict__ Wl,
                     const float* __restrict__ bias,
                     float* __restrict__ outp) {
    extern __shared__ __align__(128) char dsm[];
    const uint32_t sbase = smem_u32(dsm);
    const int tid  = threadIdx.x;
    const int wid  = tid >> 5;
    const int lane = tid & 31;
    const int bm = blockIdx.y * 128;
    const int bn = blockIdx.x * 128;
    const int wm = (wid & 3) * 32;
    const int wn = (wid >> 2) * 64;

    float acc[2][8][4];
#pragma unroll
    for (int i = 0; i < 2; i++)
#pragma unroll
        for (int j = 0; j < 8; j++)
#pragma unroll
            for (int u = 0; u < 4; u++) acc[i][j][u] = 0.0f;

    auto load_chunk = [&](int c, int b) {
        const int k0 = c * KC;
        const uint32_t bufb = sbase + b * BUF_BYTES;
        auto one = [&](const __nv_bfloat16* __restrict__ src, int row0, int toff) {
#pragma unroll
            for (int it = 0; it < 2; it++) {
                int unit = tid + it * 256;
                int row = unit >> 2;
                int q   = unit & 3;
                const void* g = src + (size_t)(row0 + row) * E_DIM + k0 + q * 8;
                uint32_t s = bufb + (uint32_t)(toff + row * PITCH + q * 8) * 2;
                cp_async16(s, g);
            }
        };
        one(Ah, bm, 0);
        one(Al, bm, TILE_ELEMS);
        one(Wh, bn, 2 * TILE_ELEMS);
        one(Wl, bn, 3 * TILE_ELEMS);
        CP_COMMIT();
    };

    load_chunk(0, 0);

    for (int c = 0; c < NCHUNK; c++) {
        const int b = c & 1;
        if (c + 1 < NCHUNK) { load_chunk(c + 1, b ^ 1); CP_WAIT1(); }
        else                { CP_WAIT0(); }
        __syncthreads();

        const uint32_t bufb = sbase + b * BUF_BYTES;
        const uint32_t aAh = bufb;
        const uint32_t aAl = bufb + TILE_ELEMS * 2;
        const uint32_t aWh = bufb + 2 * TILE_ELEMS * 2;
        const uint32_t aWl = bufb + 3 * TILE_ELEMS * 2;
        const int lrow = lane & 15;
        const int lk8  = (lane >> 4) * 8;

#pragma unroll
        for (int k16 = 0; k16 < KC / 16; k16++) {
            const int koff = k16 * 16 + lk8;
            uint32_t ah[2][4], al[2][4];
#pragma unroll
            for (int ma = 0; ma < 2; ma++) {
                uint32_t ro = (uint32_t)((wm + ma * 16 + lrow) * PITCH + koff) * 2;
                ldsm_x4(ah[ma], aAh + ro);
                ldsm_x4(al[ma], aAl + ro);
            }
#pragma unroll
            for (int ng = 0; ng < 4; ng++) {
                uint32_t ro = (uint32_t)((wn + ng * 16 + lrow) * PITCH + koff) * 2;
                uint32_t bh[4], bl[4];
                ldsm_x4(bh, aWh + ro);
                ldsm_x4(bl, aWl + ro);
#pragma unroll
                for (int ma = 0; ma < 2; ma++) {
                    mma16816(acc[ma][2 * ng],     ah[ma], bh[0], bh[2]);
                    mma16816(acc[ma][2 * ng],     ah[ma], bl[0], bl[2]);
                    mma16816(acc[ma][2 * ng],     al[ma], bh[0], bh[2]);
                    mma16816(acc[ma][2 * ng + 1], ah[ma], bh[1], bh[3]);
                    mma16816(acc[ma][2 * ng + 1], ah[ma], bl[1], bl[3]);
                    mma16816(acc[ma][2 * ng + 1], al[ma], bh[1], bh[3]);
                }
            }
        }
        __syncthreads();
    }

    const int r0 = lane >> 2;
    const int c0 = (lane & 3) * 2;
#pragma unroll
    for (int ma = 0; ma < 2; ma++) {
#pragma unroll
        for (int na = 0; na < 8; na++) {
#pragma unroll
            for (int half = 0; half < 2; half++) {
                const int m = bm + wm + ma * 16 + r0 + half * 8;
                const int f = bn + wn + na * 8 + c0;
                const float v0 = acc[ma][na][2 * half + 0] + __ldg(&bias[f]);
                const float v1 = acc[ma][na][2 * half + 1] + __ldg(&bias[f + 1]);
                if (MODE == 1) {
                    *(float2*)(outp + (size_t)m * E_DIM + f) = make_float2(v0, v1);
                } else {
                    const int t = m >> 1;
                    const int bb = m & 1;
#pragma unroll
                    for (int u = 0; u < 2; u++) {
                        const int ff = f + u;
                        float v = (u == 0) ? v0 : v1;
                        const int h  = ff / (3 * D_DIM);
                        const int r  = ff - h * (3 * D_DIM);
                        const int jj = r >> 6;
                        const int dd = r & 63;
                        const int bh = bb * H_DIM + h;
                        if (jj == 0) v *= 0.125f;                  // q pre-scale
                        __nv_bfloat16 vh = __float2bfloat16(v);
                        __nv_bfloat16 vl = __float2bfloat16(v - __bfloat162float(vh));
                        if (jj == 2) {   // V transposed: [bh][d][t]
                            const size_t idx = (((size_t)bh) * D_DIM + dd) * T_DIM + t;
                            g_Vh[idx] = vh; g_Vl[idx] = vl;
                        } else {
                            const size_t idx = (((size_t)bh) * T_DIM + t) * D_DIM + dd;
                            if (jj == 0) { g_Qh[idx] = vh; g_Ql[idx] = vl; }
                            else         { g_Kh[idx] = vh; g_Kl[idx] = vl; }
                        }
                    }
                }
            }
        }
    }
}

// ---------------------------------------------------------------------------
// Tensor-core flash attention, bf16 3-term split for QK and PV.
// CTA: 128 q-rows x one bh. 8 warps x m16. Key tiles of 64.
// Q/K: [bh][t][d]; V: [bh][d][t] (so both MMAs use non-trans ldmatrix B).
// ---------------------------------------------------------------------------
#define AS 64                       // keys per tile
#define AP 72                       // smem pitch (bf16 elems); 144B rows
#define ATILE_B (AS * AP * 2)       // 9216 B per tile
// smem map: KH=0, KL=9216, VH=18432, VL=27648; Q staging reuses [0,36864)
#define ATT_SMEM (4 * ATILE_B)

__global__ __launch_bounds__(256, 2)
void attn_mma_kernel() {
    __shared__ __align__(128) char asmem[ATT_SMEM];
    const uint32_t sbase = smem_u32(asmem);
    const int tid  = threadIdx.x;
    const int wid  = tid >> 5;
    const int lane = tid & 31;
    const int bh = blockIdx.y;
    const int q0 = blockIdx.x * 128;
    const int wq = wid * 16;                  // warp's q-row offset in tile
    const int lrow = lane & 15;
    const int lk8  = (lane >> 4) * 8;

    const __nv_bfloat16* __restrict__ Qh = g_Qh + (size_t)bh * T_DIM * D_DIM;
    const __nv_bfloat16* __restrict__ Ql = g_Ql + (size_t)bh * T_DIM * D_DIM;
    const __nv_bfloat16* __restrict__ Kh = g_Kh + (size_t)bh * T_DIM * D_DIM;
    const __nv_bfloat16* __restrict__ Kl = g_Kl + (size_t)bh * T_DIM * D_DIM;
    const __nv_bfloat16* __restrict__ Vh = g_Vh + (size_t)bh * D_DIM * T_DIM;
    const __nv_bfloat16* __restrict__ Vl = g_Vl + (size_t)bh * D_DIM * T_DIM;

    // ---- stage Q (128 x 64, hi+lo) and pull fragments into registers ----
    {
#pragma unroll
        for (int it = 0; it < 4; it++) {
            int u = tid + it * 256;           // 0..1023
            int row = u >> 3, c8 = u & 7;
            uint32_t off = (uint32_t)(row * AP + c8 * 8) * 2;
            cp_async16(sbase + off,         Qh + (size_t)(q0 + row) * D_DIM + c8 * 8);
            cp_async16(sbase + 18432 + off, Ql + (size_t)(q0 + row) * D_DIM + c8 * 8);
        }
        CP_COMMIT(); CP_WAIT0();
        __syncthreads();
    }
    uint32_t qhf[4][4], qlf[4][4];
#pragma unroll
    for (int k16 = 0; k16 < 4; k16++) {
        uint32_t ro = (uint32_t)((wq + lrow) * AP + k16 * 16 + lk8) * 2;
        ldsm_x4(qhf[k16], sbase + ro);
        ldsm_x4(qlf[k16], sbase + 18432 + ro);
    }
    __syncthreads();     // Q staging region is about to be overwritten

    float o[8][4];
#pragma unroll
    for (int i = 0; i < 8; i++)
#pragma unroll
        for (int j = 0; j < 4; j++) o[i][j] = 0.0f;
    float m0 = -INFINITY, m1 = -INFINITY, l0 = 0.0f, l1 = 0.0f;

    for (int s0 = 0; s0 < T_DIM; s0 += AS) {
        // ---- load K/V tiles (hi+lo) ----
#pragma unroll
        for (int it = 0; it < 2; it++) {
            int u = tid + it * 256;           // 0..511
            int row = u >> 3, c8 = u & 7;
            uint32_t off = (uint32_t)(row * AP + c8 * 8) * 2;
            cp_async16(sbase + 0 * ATILE_B + off, Kh + (size_t)(s0 + row) * D_DIM + c8 * 8);
            cp_async16(sbase + 1 * ATILE_B + off, Kl + (size_t)(s0 + row) * D_DIM + c8 * 8);
            cp_async16(sbase + 2 * ATILE_B + off, Vh + (size_t)row * T_DIM + s0 + c8 * 8);
            cp_async16(sbase + 3 * ATILE_B + off, Vl + (size_t)row * T_DIM + s0 + c8 * 8);
        }
        CP_COMMIT(); CP_WAIT0();
        __syncthreads();

        // ---- S = Q K^T (3-term split), 8 n8-atoms over 64 keys ----
        float s[8][4];
#pragma unroll
        for (int i = 0; i < 8; i++)
#pragma unroll
            for (int j = 0; j < 4; j++) s[i][j] = 0.0f;

#pragma unroll
        for (int k16 = 0; k16 < 4; k16++) {
            const int koff = k16 * 16 + lk8;
#pragma unroll
            for (int ng = 0; ng < 4; ng++) {
                uint32_t ro = (uint32_t)((ng * 16 + lrow) * AP + koff) * 2;
                uint32_t kh[4], kl[4];
                ldsm_x4(kh, sbase + 0 * ATILE_B + ro);
                ldsm_x4(kl, sbase + 1 * ATILE_B + ro);
                mma16816(s[2 * ng],     qhf[k16], kh[0], kh[2]);
                mma16816(s[2 * ng],     qhf[k16], kl[0], kl[2]);
                mma16816(s[2 * ng],     qlf[k16], kh[0], kh[2]);
                mma16816(s[2 * ng + 1], qhf[k16], kh[1], kh[3]);
                mma16816(s[2 * ng + 1], qhf[k16], kl[1], kl[3]);
                mma16816(s[2 * ng + 1], qlf[k16], kh[1], kh[3]);
            }
        }

        // ---- online softmax on fragment rows r=lane>>2 and r+8 ----
        float mt0 = -INFINITY, mt1 = -INFINITY;
#pragma unroll
        for (int na = 0; na < 8; na++) {
            mt0 = fmaxf(mt0, fmaxf(s[na][0], s[na][1]));
            mt1 = fmaxf(mt1, fmaxf(s[na][2], s[na][3]));
        }
        mt0 = fmaxf(mt0, __shfl_xor_sync(0xffffffff, mt0, 1));
        mt0 = fmaxf(mt0, __shfl_xor_sync(0xffffffff, mt0, 2));
        mt1 = fmaxf(mt1, __shfl_xor_sync(0xffffffff, mt1, 1));
        mt1 = fmaxf(mt1, __shfl_xor_sync(0xffffffff, mt1, 2));
        const float mn0 = fmaxf(m0, mt0);
        const float mn1 = fmaxf(m1, mt1);
        const float sc0 = __expf(m0 - mn0);
        const float sc1 = __expf(m1 - mn1);

        float ls0 = 0.0f, ls1 = 0.0f;
#pragma unroll
        for (int na = 0; na < 8; na++) {
            s[na][0] = __expf(s[na][0] - mn0);
            s[na][1] = __expf(s[na][1] - mn0);
            s[na][2] = __expf(s[na][2] - mn1);
            s[na][3] = __expf(s[na][3] - mn1);
            ls0 += s[na][0] + s[na][1];
            ls1 += s[na][2] + s[na][3];
        }
        ls0 += __shfl_xor_sync(0xffffffff, ls0, 1);
        ls0 += __shfl_xor_sync(0xffffffff, ls0, 2);
        ls1 += __shfl_xor_sync(0xffffffff, ls1, 1);
        ls1 += __shfl_xor_sync(0xffffffff, ls1, 2);
        l0 = l0 * sc0 + ls0;
        l1 = l1 * sc1 + ls1;
        m0 = mn0; m1 = mn1;
#pragma unroll
        for (int na = 0; na < 8; na++) {
            o[na][0] *= sc0; o[na][1] *= sc0;
            o[na][2] *= sc1; o[na][3] *= sc1;
        }

        // ---- O += P V (3-term split). P frags from S accum identity. ----
#pragma unroll
        for (int kg = 0; kg < 4; kg++) {       // key k16 groups
            uint32_t ph[4], pl[4];
            split2(s[2 * kg][0],     s[2 * kg][1],     ph[0], pl[0]);
            split2(s[2 * kg][2],     s[2 * kg][3],     ph[1], pl[1]);
            split2(s[2 * kg + 1][0], s[2 * kg + 1][1], ph[2], pl[2]);
            split2(s[2 * kg + 1][2], s[2 * kg + 1][3], ph[3], pl[3]);
            const int koff = kg * 16 + lk8;
#pragma unroll
            for (int ng = 0; ng < 4; ng++) {   // d n16 groups
                uint32_t ro = (uint32_t)((ng * 16 + lrow) * AP + koff) * 2;
                uint32_t vh[4], vl[4];
                ldsm_x4(vh, sbase + 2 * ATILE_B + ro);
                ldsm_x4(vl, sbase + 3 * ATILE_B + ro);
                mma16816(o[2 * ng],     ph, vh[0], vh[2]);
                mma16816(o[2 * ng],     ph, vl[0], vl[2]);
                mma16816(o[2 * ng],     pl, vh[0], vh[2]);
                mma16816(o[2 * ng + 1], ph, vh[1], vh[3]);
                mma16816(o[2 * ng + 1], ph, vl[1], vl[3]);
                mma16816(o[2 * ng + 1], pl, vh[1], vh[3]);
            }
        }
        __syncthreads();
    }

    // ---- normalize, split, write ctx [T,B,E] (e = h*64 + d) ----
    const int bsel = bh >> 4;
    const int hsel = bh & 15;
    const int rbase = lane >> 2;
    const int cc = (lane & 3) * 2;
    const float inv0 = 1.0f / l0;
    const float inv1 = 1.0f / l1;
#pragma unroll
    for (int half = 0; half < 2; half++) {
        const int t = q0 + wq + rbase + half * 8;
        const float inv = half ? inv1 : inv0;
        const size_t rowb = ((size_t)t * B_DIM + bsel) * E_DIM + hsel * D_DIM;
#pragma unroll
        for (int na = 0; na < 8; na++) {
            uint32_t hreg, lreg;
            split2(o[na][2 * half] * inv, o[na][2 * half + 1] * inv, hreg, lreg);
            const size_t idx = rowb + na * 8 + cc;
            *(uint32_t*)(g_cth + idx) = hreg;
            *(uint32_t*)(g_ctl + idx) = lreg;
        }
    }
}

// ---------------------------------------------------------------------------
extern "C" void kernel_launch(void* const* d_in, const int* in_sizes, int n_in,
                              void* d_out, int out_size) {
    const float* query = (const float*)d_in[0];   // (T,B,E)
    const float* w_in  = (const float*)d_in[1];   // (3E,E)
    const float* b_in  = (const float*)d_in[2];   // (3E,)
    const float* w_out = (const float*)d_in[3];   // (E,E)
    const float* b_out = (const float*)d_in[4];   // (E,)
    float* out = (float*)d_out;                   // (T,B,E)

    cudaFuncSetAttribute(mma_gemm_kernel<0>,
                         cudaFuncAttributeMaxDynamicSharedMemorySize, GEMM_SMEM);
    cudaFuncSetAttribute(mma_gemm_kernel<1>,
                         cudaFuncAttributeMaxDynamicSharedMemorySize, GEMM_SMEM);

    __nv_bfloat16 *qh, *ql, *wih, *wil, *woh, *wol, *cth, *ctl;
    cudaGetSymbolAddress((void**)&qh,  g_qh);
    cudaGetSymbolAddress((void**)&ql,  g_ql);
    cudaGetSymbolAddress((void**)&wih, g_wih);
    cudaGetSymbolAddress((void**)&wil, g_wil);
    cudaGetSymbolAddress((void**)&woh, g_woh);
    cudaGetSymbolAddress((void**)&wol, g_wol);
    cudaGetSymbolAddress((void**)&cth, g_cth);
    cudaGetSymbolAddress((void**)&ctl, g_ctl);

    // 1) bf16 hi/lo splits of inputs
    {
        int n = M_DIM * E_DIM;
        split_kernel<<<(n + 255) / 256, 256>>>(query, qh, ql, n);
        n = 3 * E_DIM * E_DIM;
        split_kernel<<<(n + 255) / 256, 256>>>(w_in, wih, wil, n);
        n = E_DIM * E_DIM;
        split_kernel<<<(n + 255) / 256, 256>>>(w_out, woh, wol, n);
    }

    // 2) QKV projection (tensor cores), split-scatter epilogue
    {
        dim3 g(3 * E_DIM / 128, M_DIM / 128);   // 24 x 32
        mma_gemm_kernel<0><<<g, 256, GEMM_SMEM>>>(qh, ql, wih, wil, b_in, nullptr);
    }

    // 3) attention (tensor cores, split QK + split PV)
    {
        dim3 g(T_DIM / 128, B_DIM * H_DIM);     // 16 x 32
        attn_mma_kernel<<<g, 256>>>();
    }

    // 4) output projection (tensor cores)
    {
        dim3 g(E_DIM / 128, M_DIM / 128);       // 8 x 32
        mma_gemm_kernel<1><<<g, 256, GEMM_SMEM>>>(cth, ctl, woh, wol, b_out, out);
    }
}

// round 17
// speedup vs baseline: 2.8001x; 1.0085x over previous
#include <cuda_runtime.h>
#include <cuda_bf16.h>
#include <cstdint>
#include <math.h>

// Fixed problem shapes
#define T_DIM 2048
#define B_DIM 2
#define E_DIM 1024
#define H_DIM 16
#define D_DIM 64
#define M_DIM (T_DIM * B_DIM)   // 4096 rows for projections

__device__ __forceinline__ uint32_t smem_u32(const void* p) {
    uint32_t a;
    asm("{ .reg .u64 t; cvta.to.shared.u64 t, %1; cvt.u32.u64 %0, t; }"
        : "=r"(a) : "l"(p));
    return a;
}

// ---- portable tensor-core primitives (no 'a'-suffix features) -------------
__device__ __forceinline__ void ldsm_x4(uint32_t r[4], uint32_t addr) {
    asm volatile("ldmatrix.sync.aligned.m8n8.x4.shared.b16 {%0,%1,%2,%3}, [%4];"
                 : "=r"(r[0]), "=r"(r[1]), "=r"(r[2]), "=r"(r[3]) : "r"(addr));
}
__device__ __forceinline__ void mma16816(float c[4], const uint32_t a[4],
                                         uint32_t b0, uint32_t b1) {
    asm volatile(
        "mma.sync.aligned.m16n8k16.row.col.f32.bf16.bf16.f32 "
        "{%0,%1,%2,%3}, {%4,%5,%6,%7}, {%8,%9}, {%0,%1,%2,%3};"
        : "+f"(c[0]), "+f"(c[1]), "+f"(c[2]), "+f"(c[3])
        : "r"(a[0]), "r"(a[1]), "r"(a[2]), "r"(a[3]), "r"(b0), "r"(b1));
}
__device__ __forceinline__ void cp_async16(uint32_t saddr, const void* gaddr) {
    asm volatile("cp.async.cg.shared.global [%0], [%1], 16;"
                 :: "r"(saddr), "l"(gaddr));
}
#define CP_COMMIT() asm volatile("cp.async.commit_group;" ::: "memory")
#define CP_WAIT0()  asm volatile("cp.async.wait_group 0;" ::: "memory")
#define CP_WAIT1()  asm volatile("cp.async.wait_group 1;" ::: "memory")

// bf16x2 pack / hi-lo split helpers
__device__ __forceinline__ void split2(float x, float y, uint32_t& h, uint32_t& l) {
    __nv_bfloat162 hb = __float22bfloat162_rn(make_float2(x, y));
    float2 hf = __bfloat1622float2(hb);
    __nv_bfloat162 lb = __float22bfloat162_rn(make_float2(x - hf.x, y - hf.y));
    h = *reinterpret_cast<uint32_t*>(&hb);
    l = *reinterpret_cast<uint32_t*>(&lb);
}

// ---- scratch (__device__ globals; allocation-free rule) -------------------
__device__ __nv_bfloat16 g_Qh[32 * T_DIM * D_DIM], g_Ql[32 * T_DIM * D_DIM]; // [bh][t][d]
__device__ __nv_bfloat16 g_Kh[32 * T_DIM * D_DIM], g_Kl[32 * T_DIM * D_DIM]; // [bh][t][d]
__device__ __nv_bfloat16 g_Vh[32 * D_DIM * T_DIM], g_Vl[32 * D_DIM * T_DIM]; // [bh][d][t]

__device__ __nv_bfloat16 g_qh[M_DIM * E_DIM],  g_ql[M_DIM * E_DIM];
__device__ __nv_bfloat16 g_wih[3 * E_DIM * E_DIM], g_wil[3 * E_DIM * E_DIM];
__device__ __nv_bfloat16 g_woh[E_DIM * E_DIM], g_wol[E_DIM * E_DIM];
__device__ __nv_bfloat16 g_cth[M_DIM * E_DIM], g_ctl[M_DIM * E_DIM];

// ---------------------------------------------------------------------------
// Split fp32 -> bf16 hi + bf16 lo
// ---------------------------------------------------------------------------
__global__ void split_kernel(const float* __restrict__ src,
                             __nv_bfloat16* __restrict__ h,
                             __nv_bfloat16* __restrict__ l, int n) {
    int i = blockIdx.x * 256 + threadIdx.x;
    if (i < n) {
        float x = src[i];
        __nv_bfloat16 hh = __float2bfloat16(x);
        h[i] = hh;
        l[i] = __float2bfloat16(x - __bfloat162float(hh));
    }
}

// ---------------------------------------------------------------------------
// mma.sync GEMM: C[m,f] = sum_e A[m,e]*W[f,e] + bias[f]
// bf16 3-term split, fp32 accum. CTA 128x128, 8 warps, K-chunk 32, cp.async
// double-buffered smem AND double-buffered B ldmatrix fragments.
// MODE 0: QKV split-scatter epilogue. MODE 1: plain store.
// ---------------------------------------------------------------------------
#define KC 32
#define PITCH 40
#define TILE_ELEMS (128 * PITCH)
#define BUF_ELEMS (4 * TILE_ELEMS)
#define BUF_BYTES (BUF_ELEMS * 2)
#define GEMM_SMEM (2 * BUF_BYTES)
#define NCHUNK (E_DIM / KC)

template <int MODE>
__global__ __launch_bounds__(256, 2)
void mma_gemm_kernel(const __nv_bfloat16* __restrict__ Ah,
                     const __nv_bfloat16* __restrict__ Al,
                     const __nv_bfloat16* __restrict__ Wh,
                     const __nv_bfloat16* __restrict__ Wl,
                     const float* __restrict__ bias,
                     float* __restrict__ outp) {
    extern __shared__ __align__(128) char dsm[];
    const uint32_t sbase = smem_u32(dsm);
    const int tid  = threadIdx.x;
    const int wid  = tid >> 5;
    const int lane = tid & 31;
    const int bm = blockIdx.y * 128;
    const int bn = blockIdx.x * 128;
    const int wm = (wid & 3) * 32;
    const int wn = (wid >> 2) * 64;

    float acc[2][8][4];
#pragma unroll
    for (int i = 0; i < 2; i++)
#pragma unroll
        for (int j = 0; j < 8; j++)
#pragma unroll
            for (int u = 0; u < 4; u++) acc[i][j][u] = 0.0f;

    auto load_chunk = [&](int c, int b) {
        const int k0 = c * KC;
        const uint32_t bufb = sbase + b * BUF_BYTES;
        auto one = [&](const __nv_bfloat16* __restrict__ src, int row0, int toff) {
#pragma unroll
            for (int it = 0; it < 2; it++) {
                int unit = tid + it * 256;
                int row = unit >> 2;
                int q   = unit & 3;
                const void* g = src + (size_t)(row0 + row) * E_DIM + k0 + q * 8;
                uint32_t s = bufb + (uint32_t)(toff + row * PITCH + q * 8) * 2;
                cp_async16(s, g);
            }
        };
        one(Ah, bm, 0);
        one(Al, bm, TILE_ELEMS);
        one(Wh, bn, 2 * TILE_ELEMS);
        one(Wl, bn, 3 * TILE_ELEMS);
        CP_COMMIT();
    };

    load_chunk(0, 0);

    const int lrow = lane & 15;
    const int lk8  = (lane >> 4) * 8;

    for (int c = 0; c < NCHUNK; c++) {
        const int b = c & 1;
        if (c + 1 < NCHUNK) { load_chunk(c + 1, b ^ 1); CP_WAIT1(); }
        else                { CP_WAIT0(); }
        __syncthreads();

        const uint32_t bufb = sbase + b * BUF_BYTES;
        const uint32_t aAh = bufb;
        const uint32_t aAl = bufb + TILE_ELEMS * 2;
        const uint32_t aWh = bufb + 2 * TILE_ELEMS * 2;
        const uint32_t aWl = bufb + 3 * TILE_ELEMS * 2;

#pragma unroll
        for (int k16 = 0; k16 < KC / 16; k16++) {
            const int koff = k16 * 16 + lk8;
            uint32_t ah[2][4], al[2][4];
#pragma unroll
            for (int ma = 0; ma < 2; ma++) {
                uint32_t ro = (uint32_t)((wm + ma * 16 + lrow) * PITCH + koff) * 2;
                ldsm_x4(ah[ma], aAh + ro);
                ldsm_x4(al[ma], aAl + ro);
            }
            // double-buffered B fragments: prefetch ng+1 during ng's MMAs
            uint32_t bh[2][4], bl[2][4];
            {
                uint32_t ro = (uint32_t)((wn + lrow) * PITCH + koff) * 2;
                ldsm_x4(bh[0], aWh + ro);
                ldsm_x4(bl[0], aWl + ro);
            }
#pragma unroll
            for (int ng = 0; ng < 4; ng++) {
                const int cur = ng & 1;
                const int nxt = cur ^ 1;
                if (ng < 3) {
                    uint32_t ro =
                        (uint32_t)((wn + (ng + 1) * 16 + lrow) * PITCH + koff) * 2;
                    ldsm_x4(bh[nxt], aWh + ro);
                    ldsm_x4(bl[nxt], aWl + ro);
                }
#pragma unroll
                for (int ma = 0; ma < 2; ma++) {
                    mma16816(acc[ma][2 * ng],     ah[ma], bh[cur][0], bh[cur][2]);
                    mma16816(acc[ma][2 * ng],     ah[ma], bl[cur][0], bl[cur][2]);
                    mma16816(acc[ma][2 * ng],     al[ma], bh[cur][0], bh[cur][2]);
                    mma16816(acc[ma][2 * ng + 1], ah[ma], bh[cur][1], bh[cur][3]);
                    mma16816(acc[ma][2 * ng + 1], ah[ma], bl[cur][1], bl[cur][3]);
                    mma16816(acc[ma][2 * ng + 1], al[ma], bh[cur][1], bh[cur][3]);
                }
            }
        }
        __syncthreads();
    }

    const int r0 = lane >> 2;
    const int c0 = (lane & 3) * 2;
#pragma unroll
    for (int ma = 0; ma < 2; ma++) {
#pragma unroll
        for (int na = 0; na < 8; na++) {
#pragma unroll
            for (int half = 0; half < 2; half++) {
                const int m = bm + wm + ma * 16 + r0 + half * 8;
                const int f = bn + wn + na * 8 + c0;
                const float v0 = acc[ma][na][2 * half + 0] + __ldg(&bias[f]);
                const float v1 = acc[ma][na][2 * half + 1] + __ldg(&bias[f + 1]);
                if (MODE == 1) {
                    *(float2*)(outp + (size_t)m * E_DIM + f) = make_float2(v0, v1);
                } else {
                    const int t = m >> 1;
                    const int bb = m & 1;
#pragma unroll
                    for (int u = 0; u < 2; u++) {
                        const int ff = f + u;
                        float v = (u == 0) ? v0 : v1;
                        const int h  = ff / (3 * D_DIM);
                        const int r  = ff - h * (3 * D_DIM);
                        const int jj = r >> 6;
                        const int dd = r & 63;
                        const int bh = bb * H_DIM + h;
                        if (jj == 0) v *= 0.125f;                  // q pre-scale
                        __nv_bfloat16 vh = __float2bfloat16(v);
                        __nv_bfloat16 vl = __float2bfloat16(v - __bfloat162float(vh));
                        if (jj == 2) {   // V transposed: [bh][d][t]
                            const size_t idx = (((size_t)bh) * D_DIM + dd) * T_DIM + t;
                            g_Vh[idx] = vh; g_Vl[idx] = vl;
                        } else {
                            const size_t idx = (((size_t)bh) * T_DIM + t) * D_DIM + dd;
                            if (jj == 0) { g_Qh[idx] = vh; g_Ql[idx] = vl; }
                            else         { g_Kh[idx] = vh; g_Kl[idx] = vl; }
                        }
                    }
                }
            }
        }
    }
}

// ---------------------------------------------------------------------------
// Tensor-core flash attention, bf16 3-term split for QK and PV.
// CTA: 128 q-rows x one bh. 8 warps x m16. Key tiles of 64.
// Q/K: [bh][t][d]; V: [bh][d][t]. K/V tiles double-buffered via cp.async.
// ---------------------------------------------------------------------------
#define AS 64                       // keys per tile
#define AP 72                       // smem pitch (bf16 elems); 144B rows
#define ATILE_B (AS * AP * 2)       // 9216 B per tile
#define AKV_B (4 * ATILE_B)         // KH, KL, VH, VL = 36864 B per buffer
#define ATT_SMEM (2 * AKV_B)        // double-buffered = 73728 B
#define N_STILE (T_DIM / AS)        // 32

__global__ __launch_bounds__(256, 2)
void attn_mma_kernel() {
    extern __shared__ __align__(128) char asmem[];
    const uint32_t sbase = smem_u32(asmem);
    const int tid  = threadIdx.x;
    const int wid  = tid >> 5;
    const int lane = tid & 31;
    const int bh = blockIdx.y;
    const int q0 = blockIdx.x * 128;
    const int wq = wid * 16;                  // warp's q-row offset in tile
    const int lrow = lane & 15;
    const int lk8  = (lane >> 4) * 8;

    const __nv_bfloat16* __restrict__ Qh = g_Qh + (size_t)bh * T_DIM * D_DIM;
    const __nv_bfloat16* __restrict__ Ql = g_Ql + (size_t)bh * T_DIM * D_DIM;
    const __nv_bfloat16* __restrict__ Kh = g_Kh + (size_t)bh * T_DIM * D_DIM;
    const __nv_bfloat16* __restrict__ Kl = g_Kl + (size_t)bh * T_DIM * D_DIM;
    const __nv_bfloat16* __restrict__ Vh = g_Vh + (size_t)bh * D_DIM * T_DIM;
    const __nv_bfloat16* __restrict__ Vl = g_Vl + (size_t)bh * D_DIM * T_DIM;

    // ---- stage Q (128 x 64, hi+lo) in buffer 0, pull fragments ----
    {
#pragma unroll
        for (int it = 0; it < 4; it++) {
            int u = tid + it * 256;           // 0..1023
            int row = u >> 3, c8 = u & 7;
            uint32_t off = (uint32_t)(row * AP + c8 * 8) * 2;
            cp_async16(sbase + off,         Qh + (size_t)(q0 + row) * D_DIM + c8 * 8);
            cp_async16(sbase + 18432 + off, Ql + (size_t)(q0 + row) * D_DIM + c8 * 8);
        }
        CP_COMMIT(); CP_WAIT0();
        __syncthreads();
    }
    uint32_t qhf[4][4], qlf[4][4];
#pragma unroll
    for (int k16 = 0; k16 < 4; k16++) {
        uint32_t ro = (uint32_t)((wq + lrow) * AP + k16 * 16 + lk8) * 2;
        ldsm_x4(qhf[k16], sbase + ro);
        ldsm_x4(qlf[k16], sbase + 18432 + ro);
    }
    __syncthreads();     // Q staging region about to be reused for K/V

    // K/V tile loader into buffer bsel
    auto load_kv = [&](int s0, int bsel) {
        const uint32_t bb = sbase + bsel * AKV_B;
#pragma unroll
        for (int it = 0; it < 2; it++) {
            int u = tid + it * 256;           // 0..511
            int row = u >> 3, c8 = u & 7;
            uint32_t off = (uint32_t)(row * AP + c8 * 8) * 2;
            cp_async16(bb + 0 * ATILE_B + off, Kh + (size_t)(s0 + row) * D_DIM + c8 * 8);
            cp_async16(bb + 1 * ATILE_B + off, Kl + (size_t)(s0 + row) * D_DIM + c8 * 8);
            cp_async16(bb + 2 * ATILE_B + off, Vh + (size_t)row * T_DIM + s0 + c8 * 8);
            cp_async16(bb + 3 * ATILE_B + off, Vl + (size_t)row * T_DIM + s0 + c8 * 8);
        }
        CP_COMMIT();
    };

    float o[8][4];
#pragma unroll
    for (int i = 0; i < 8; i++)
#pragma unroll
        for (int j = 0; j < 4; j++) o[i][j] = 0.0f;
    float m0 = -INFINITY, m1 = -INFINITY, l0 = 0.0f, l1 = 0.0f;

    load_kv(0, 0);

    for (int it = 0; it < N_STILE; it++) {
        const int b = it & 1;
        if (it + 1 < N_STILE) { load_kv((it + 1) * AS, b ^ 1); CP_WAIT1(); }
        else                  { CP_WAIT0(); }
        __syncthreads();

        const uint32_t bb = sbase + b * AKV_B;

        // ---- S = Q K^T (3-term split), 8 n8-atoms over 64 keys ----
        float s[8][4];
#pragma unroll
        for (int i = 0; i < 8; i++)
#pragma unroll
            for (int j = 0; j < 4; j++) s[i][j] = 0.0f;

#pragma unroll
        for (int k16 = 0; k16 < 4; k16++) {
            const int koff = k16 * 16 + lk8;
#pragma unroll
            for (int ng = 0; ng < 4; ng++) {
                uint32_t ro = (uint32_t)((ng * 16 + lrow) * AP + koff) * 2;
                uint32_t kh[4], kl[4];
                ldsm_x4(kh, bb + 0 * ATILE_B + ro);
                ldsm_x4(kl, bb + 1 * ATILE_B + ro);
                mma16816(s[2 * ng],     qhf[k16], kh[0], kh[2]);
                mma16816(s[2 * ng],     qhf[k16], kl[0], kl[2]);
                mma16816(s[2 * ng],     qlf[k16], kh[0], kh[2]);
                mma16816(s[2 * ng + 1], qhf[k16], kh[1], kh[3]);
                mma16816(s[2 * ng + 1], qhf[k16], kl[1], kl[3]);
                mma16816(s[2 * ng + 1], qlf[k16], kh[1], kh[3]);
            }
        }

        // ---- online softmax on fragment rows r=lane>>2 and r+8 ----
        float mt0 = -INFINITY, mt1 = -INFINITY;
#pragma unroll
        for (int na = 0; na < 8; na++) {
            mt0 = fmaxf(mt0, fmaxf(s[na][0], s[na][1]));
            mt1 = fmaxf(mt1, fmaxf(s[na][2], s[na][3]));
        }
        mt0 = fmaxf(mt0, __shfl_xor_sync(0xffffffff, mt0, 1));
        mt0 = fmaxf(mt0, __shfl_xor_sync(0xffffffff, mt0, 2));
        mt1 = fmaxf(mt1, __shfl_xor_sync(0xffffffff, mt1, 1));
        mt1 = fmaxf(mt1, __shfl_xor_sync(0xffffffff, mt1, 2));
        const float mn0 = fmaxf(m0, mt0);
        const float mn1 = fmaxf(m1, mt1);
        const float sc0 = __expf(m0 - mn0);
        const float sc1 = __expf(m1 - mn1);

        float ls0 = 0.0f, ls1 = 0.0f;
#pragma unroll
        for (int na = 0; na < 8; na++) {
            s[na][0] = __expf(s[na][0] - mn0);
            s[na][1] = __expf(s[na][1] - mn0);
            s[na][2] = __expf(s[na][2] - mn1);
            s[na][3] = __expf(s[na][3] - mn1);
            ls0 += s[na][0] + s[na][1];
            ls1 += s[na][2] + s[na][3];
        }
        ls0 += __shfl_xor_sync(0xffffffff, ls0, 1);
        ls0 += __shfl_xor_sync(0xffffffff, ls0, 2);
        ls1 += __shfl_xor_sync(0xffffffff, ls1, 1);
        ls1 += __shfl_xor_sync(0xffffffff, ls1, 2);
        l0 = l0 * sc0 + ls0;
        l1 = l1 * sc1 + ls1;
        m0 = mn0; m1 = mn1;
#pragma unroll
        for (int na = 0; na < 8; na++) {
            o[na][0] *= sc0; o[na][1] *= sc0;
            o[na][2] *= sc1; o[na][3] *= sc1;
        }

        // ---- O += P V (3-term split). P frags from S accum identity. ----
#pragma unroll
        for (int kg = 0; kg < 4; kg++) {       // key k16 groups
            uint32_t ph[4], pl[4];
            split2(s[2 * kg][0],     s[2 * kg][1],     ph[0], pl[0]);
            split2(s[2 * kg][2],     s[2 * kg][3],     ph[1], pl[1]);
            split2(s[2 * kg + 1][0], s[2 * kg + 1][1], ph[2], pl[2]);
            split2(s[2 * kg + 1][2], s[2 * kg + 1][3], ph[3], pl[3]);
            const int koff = kg * 16 + lk8;
#pragma unroll
            for (int ng = 0; ng < 4; ng++) {   // d n16 groups
                uint32_t ro = (uint32_t)((ng * 16 + lrow) * AP + koff) * 2;
                uint32_t vh[4], vl[4];
                ldsm_x4(vh, bb + 2 * ATILE_B + ro);
                ldsm_x4(vl, bb + 3 * ATILE_B + ro);
                mma16816(o[2 * ng],     ph, vh[0], vh[2]);
                mma16816(o[2 * ng],     ph, vl[0], vl[2]);
                mma16816(o[2 * ng],     pl, vh[0], vh[2]);
                mma16816(o[2 * ng + 1], ph, vh[1], vh[3]);
                mma16816(o[2 * ng + 1], ph, vl[1], vl[3]);
                mma16816(o[2 * ng + 1], pl, vh[1], vh[3]);
            }
        }
        __syncthreads();
    }

    // ---- normalize, split, write ctx [T,B,E] (e = h*64 + d) ----
    const int bsel = bh >> 4;
    const int hsel = bh & 15;
    const int rbase = lane >> 2;
    const int cc = (lane & 3) * 2;
    const float inv0 = 1.0f / l0;
    const float inv1 = 1.0f / l1;
#pragma unroll
    for (int half = 0; half < 2; half++) {
        const int t = q0 + wq + rbase + half * 8;
        const float inv = half ? inv1 : inv0;
        const size_t rowb = ((size_t)t * B_DIM + bsel) * E_DIM + hsel * D_DIM;
#pragma unroll
        for (int na = 0; na < 8; na++) {
            uint32_t hreg, lreg;
            split2(o[na][2 * half] * inv, o[na][2 * half + 1] * inv, hreg, lreg);
            const size_t idx = rowb + na * 8 + cc;
            *(uint32_t*)(g_cth + idx) = hreg;
            *(uint32_t*)(g_ctl + idx) = lreg;
        }
    }
}

// ---------------------------------------------------------------------------
extern "C" void kernel_launch(void* const* d_in, const int* in_sizes, int n_in,
                              void* d_out, int out_size) {
    const float* query = (const float*)d_in[0];   // (T,B,E)
    const float* w_in  = (const float*)d_in[1];   // (3E,E)
    const float* b_in  = (const float*)d_in[2];   // (3E,)
    const float* w_out = (const float*)d_in[3];   // (E,E)
    const float* b_out = (const float*)d_in[4];   // (E,)
    float* out = (float*)d_out;                   // (T,B,E)

    cudaFuncSetAttribute(mma_gemm_kernel<0>,
                         cudaFuncAttributeMaxDynamicSharedMemorySize, GEMM_SMEM);
    cudaFuncSetAttribute(mma_gemm_kernel<1>,
                         cudaFuncAttributeMaxDynamicSharedMemorySize, GEMM_SMEM);
    cudaFuncSetAttribute(attn_mma_kernel,
                         cudaFuncAttributeMaxDynamicSharedMemorySize, ATT_SMEM);

    __nv_bfloat16 *qh, *ql, *wih, *wil, *woh, *wol, *cth, *ctl;
    cudaGetSymbolAddress((void**)&qh,  g_qh);
    cudaGetSymbolAddress((void**)&ql,  g_ql);
    cudaGetSymbolAddress((void**)&wih, g_wih);
    cudaGetSymbolAddress((void**)&wil, g_wil);
    cudaGetSymbolAddress((void**)&woh, g_woh);
    cudaGetSymbolAddress((void**)&wol, g_wol);
    cudaGetSymbolAddress((void**)&cth, g_cth);
    cudaGetSymbolAddress((void**)&ctl, g_ctl);

    // 1) bf16 hi/lo splits of inputs
    {
        int n = M_DIM * E_DIM;
        split_kernel<<<(n + 255) / 256, 256>>>(query, qh, ql, n);
        n = 3 * E_DIM * E_DIM;
        split_kernel<<<(n + 255) / 256, 256>>>(w_in, wih, wil, n);
        n = E_DIM * E_DIM;
        split_kernel<<<(n + 255) / 256, 256>>>(w_out, woh, wol, n);
    }

    // 2) QKV projection (tensor cores), split-scatter epilogue
    {
        dim3 g(3 * E_DIM / 128, M_DIM / 128);   // 24 x 32
        mma_gemm_kernel<0><<<g, 256, GEMM_SMEM>>>(qh, ql, wih, wil, b_in, nullptr);
    }

    // 3) attention (tensor cores, split QK + split PV, double-buffered K/V)
    {
        dim3 g(T_DIM / 128, B_DIM * H_DIM);     // 16 x 32
        attn_mma_kernel<<<g, 256, ATT_SMEM>>>();
    }

    // 4) output projection (tensor cores)
    {
        dim3 g(E_DIM / 128, M_DIM / 128);       // 8 x 32
        mma_gemm_kernel<1><<<g, 256, GEMM_SMEM>>>(cth, ctl, woh, wol, b_out, out);
    }
}